// round 1
// baseline (speedup 1.0000x reference)
#include <cuda_runtime.h>
#include <cuda_bf16.h>
#include <math.h>
#include <stdint.h>

// ---------------------------------------------------------------------------
// Problem constants
// ---------------------------------------------------------------------------
#define Bm 256
#define Lm 200
#define Hm 768
#define Dm 64
#define NS 6
#define Mseq (Bm * Lm)          // 51200

// ---------------------------------------------------------------------------
// Device scratch (static globals — no allocation allowed)
// ---------------------------------------------------------------------------
__device__ float g_E[(size_t)Mseq * Dm];            // 13.1 MB   E = ev@We+be
__device__ float g_G[(size_t)6 * Mseq * Dm];        // 78.6 MB   activated gates (gate, row, d)
__device__ float g_Hs[(size_t)Mseq * Dm];           // 13.1 MB   hidden states
__device__ float g_Ec[Bm * Dm];
__device__ float g_Gc[6 * Bm * Dm];
__device__ float g_Clast[Bm * Dm];
__device__ float g_Hcur[Bm * Dm];
__device__ float g_wt[384];                          // Wtime @ Wg_bot
__device__ float g_bias[384];                        // btime @ Wg_bot + bg

// ---------------------------------------------------------------------------
// Math helpers
// ---------------------------------------------------------------------------
__device__ __forceinline__ float fast_tanh(float x) {
    float y;
    asm("tanh.approx.f32 %0, %1;" : "=f"(y) : "f"(x));
    return y;
}
__device__ __forceinline__ float fsigmoid(float x) {
    return __fdividef(1.0f, 1.0f + __expf(-x));
}
__device__ __forceinline__ float fsoftplus(float x) {
    return fmaxf(x, 0.0f) + log1pf(__expf(-fabsf(x)));
}
__device__ __forceinline__ float fgelu(float x) {
    return 0.5f * x * (1.0f + erff(x * 0.70710678118654752f));
}

// ---------------------------------------------------------------------------
// Setup: wt_row[c] = sum_d Wtime[d]*Wg[64+d, c];  bias_row[c] = sum_d btime[d]*Wg[64+d,c] + bg[c]
// ---------------------------------------------------------------------------
__global__ void setup_kernel(const float* __restrict__ Wtime, const float* __restrict__ btime,
                             const float* __restrict__ Wg, const float* __restrict__ bg) {
    int c = threadIdx.x;   // 384 threads
    float s1 = 0.f, s2 = 0.f;
    #pragma unroll 8
    for (int d = 0; d < 64; d++) {
        float w = Wg[(size_t)(64 + d) * 384 + c];
        s1 += Wtime[d] * w;
        s2 += btime[d] * w;
    }
    g_wt[c] = s1;
    g_bias[c] = s2 + bg[c];
}

// ---------------------------------------------------------------------------
// GEMM1: C[M,64] = A[M,768] @ We[768,64] + be    (M multiple of 128)
// Tile: BM=128, BN=64, BK=16, 256 threads, 8x4 per thread.
// ---------------------------------------------------------------------------
__global__ __launch_bounds__(256) void gemm1_kernel(const float* __restrict__ A,
                                                    const float* __restrict__ We,
                                                    const float* __restrict__ be,
                                                    float* __restrict__ C) {
    __shared__ float As[16][132];   // transposed [k][m], padded
    __shared__ float Bs[16][64];
    const int tid = threadIdx.x;
    const size_t r0 = (size_t)blockIdx.x * 128;
    const int mrow = (tid >> 4) * 8;   // 0..120
    const int ncol = (tid & 15) * 4;   // 0..60

    float acc[8][4];
    #pragma unroll
    for (int i = 0; i < 8; i++)
        #pragma unroll
        for (int j = 0; j < 4; j++) acc[i][j] = 0.f;

    for (int k0 = 0; k0 < 768; k0 += 16) {
        #pragma unroll
        for (int p = 0; p < 2; p++) {
            int idx = tid + p * 256;
            int m = idx >> 2;
            int kv = (idx & 3) * 4;
            float4 v = *reinterpret_cast<const float4*>(A + (r0 + m) * 768 + k0 + kv);
            As[kv + 0][m] = v.x;
            As[kv + 1][m] = v.y;
            As[kv + 2][m] = v.z;
            As[kv + 3][m] = v.w;
        }
        {
            int k = tid >> 4;
            int nv = (tid & 15) * 4;
            float4 v = *reinterpret_cast<const float4*>(We + (size_t)(k0 + k) * 64 + nv);
            *reinterpret_cast<float4*>(&Bs[k][nv]) = v;
        }
        __syncthreads();
        #pragma unroll
        for (int kk = 0; kk < 16; kk++) {
            float a[8], b[4];
            #pragma unroll
            for (int i = 0; i < 8; i++) a[i] = As[kk][mrow + i];
            #pragma unroll
            for (int j = 0; j < 4; j++) b[j] = Bs[kk][ncol + j];
            #pragma unroll
            for (int i = 0; i < 8; i++)
                #pragma unroll
                for (int j = 0; j < 4; j++) acc[i][j] = fmaf(a[i], b[j], acc[i][j]);
        }
        __syncthreads();
    }
    float bb[4];
    #pragma unroll
    for (int j = 0; j < 4; j++) bb[j] = be[ncol + j];
    #pragma unroll
    for (int i = 0; i < 8; i++) {
        float4 v;
        v.x = acc[i][0] + bb[0];
        v.y = acc[i][1] + bb[1];
        v.z = acc[i][2] + bb[2];
        v.w = acc[i][3] + bb[3];
        *reinterpret_cast<float4*>(C + (r0 + mrow + i) * 64 + ncol) = v;
    }
}

// ---------------------------------------------------------------------------
// GEMM2: gates = act( E[M,64] @ Wg_top[64,384] + days[row]*wt_row + bias_row )
// Written as 6 planes: gates[(gate*M + row)*64 + d]  with activation per gate.
// Tile: BM=128, BN=128, K=64 full, BK=16, 256 threads, 8x8 interleaved.
// M multiple of 128 for the load path? (M=256 and 51200 both multiples of 128.)
// ---------------------------------------------------------------------------
__global__ __launch_bounds__(256) void gemm2_kernel(const float* __restrict__ E,
                                                    const float* __restrict__ Wg,
                                                    const float* __restrict__ days,
                                                    float* __restrict__ gates, int M) {
    __shared__ float As[16][132];
    __shared__ float Bs[16][128];
    const int tid = threadIdx.x;
    const size_t r0 = (size_t)blockIdx.x * 128;
    const int n0 = blockIdx.y * 128;
    const int m0 = (tid >> 4) * 4;    // 0..60
    const int c0 = (tid & 15) * 4;    // 0..60

    float acc[2][2][4][4];
    #pragma unroll
    for (int hi = 0; hi < 2; hi++)
        #pragma unroll
        for (int hj = 0; hj < 2; hj++)
            #pragma unroll
            for (int i = 0; i < 4; i++)
                #pragma unroll
                for (int j = 0; j < 4; j++) acc[hi][hj][i][j] = 0.f;

    for (int k0 = 0; k0 < 64; k0 += 16) {
        #pragma unroll
        for (int p = 0; p < 2; p++) {
            int idx = tid + p * 256;
            int m = idx >> 2;
            int kv = (idx & 3) * 4;
            float4 v = *reinterpret_cast<const float4*>(E + (r0 + m) * 64 + k0 + kv);
            As[kv + 0][m] = v.x;
            As[kv + 1][m] = v.y;
            As[kv + 2][m] = v.z;
            As[kv + 3][m] = v.w;
        }
        #pragma unroll
        for (int p = 0; p < 2; p++) {
            int idx = tid + p * 256;
            int k = idx >> 5;
            int nv = (idx & 31) * 4;
            *reinterpret_cast<float4*>(&Bs[k][nv]) =
                *reinterpret_cast<const float4*>(Wg + (size_t)(k0 + k) * 384 + n0 + nv);
        }
        __syncthreads();
        #pragma unroll
        for (int kk = 0; kk < 16; kk++) {
            float a[2][4], b[2][4];
            #pragma unroll
            for (int hi = 0; hi < 2; hi++)
                #pragma unroll
                for (int i = 0; i < 4; i++) a[hi][i] = As[kk][hi * 64 + m0 + i];
            #pragma unroll
            for (int hj = 0; hj < 2; hj++)
                #pragma unroll
                for (int j = 0; j < 4; j++) b[hj][j] = Bs[kk][hj * 64 + c0 + j];
            #pragma unroll
            for (int hi = 0; hi < 2; hi++)
                #pragma unroll
                for (int i = 0; i < 4; i++)
                    #pragma unroll
                    for (int hj = 0; hj < 2; hj++)
                        #pragma unroll
                        for (int j = 0; j < 4; j++)
                            acc[hi][hj][i][j] = fmaf(a[hi][i], b[hj][j], acc[hi][hj][i][j]);
        }
        __syncthreads();
    }

    // Epilogue: bias + rank-1 time term + per-gate activation, float4 stores.
    #pragma unroll
    for (int hi = 0; hi < 2; hi++) {
        #pragma unroll
        for (int i = 0; i < 4; i++) {
            size_t rg = r0 + hi * 64 + m0 + i;
            float dy = days ? days[rg] : 0.f;
            #pragma unroll
            for (int hj = 0; hj < 2; hj++) {
                int cg = n0 + hj * 64 + c0;         // aligned: 4-col group within one gate
                int gate = cg >> 6;
                int d = cg & 63;
                float v[4];
                #pragma unroll
                for (int j = 0; j < 4; j++)
                    v[j] = acc[hi][hj][i][j] + g_bias[cg + j] + dy * g_wt[cg + j];
                if (gate == 2) {
                    #pragma unroll
                    for (int j = 0; j < 4; j++) v[j] = fast_tanh(v[j]);
                } else if (gate == 4) {
                    #pragma unroll
                    for (int j = 0; j < 4; j++) v[j] = fsoftplus(v[j]);
                } else if (gate != 5) {   // 0,1,3 -> sigmoid
                    #pragma unroll
                    for (int j = 0; j < 4; j++) v[j] = fsigmoid(v[j]);
                }
                float4 st = make_float4(v[0], v[1], v[2], v[3]);
                *reinterpret_cast<float4*>(gates + ((size_t)gate * M + rg) * 64 + d) = st;
            }
        }
    }
}

// ---------------------------------------------------------------------------
// Sequential CT-LSTM scan.  One thread per (b,d).  Carry chain = 1 FMA/step.
// ---------------------------------------------------------------------------
__global__ __launch_bounds__(256) void scan_kernel(const float* __restrict__ gates,
                                                   const float* __restrict__ days) {
    int t = blockIdx.x * blockDim.x + threadIdx.x;   // 0..16383
    int b = t >> 6, d = t & 63;
    const size_t S = (size_t)Mseq * 64;
    size_t base = ((size_t)b * Lm) * 64 + d;
    float c = 0.f;
    #pragma unroll 4
    for (int l = 0; l < Lm; l++) {
        size_t idx = base + (size_t)l * 64;
        float i_ = gates[idx];
        float f_ = gates[S + idx];
        float z_ = gates[2 * S + idx];
        float o_ = gates[3 * S + idx];
        float dl = gates[4 * S + idx];
        float cb = gates[5 * S + idx];
        float dt = fmaxf(days[b * Lm + l], 0.f);
        c = f_ * c + i_ * z_;
        float e = __expf(-dl * dt);
        float cd = cb + (c - cb) * e;
        g_Hs[idx] = o_ * fast_tanh(cd);
    }
    g_Clast[b * 64 + d] = c;
}

// ---------------------------------------------------------------------------
// Final CT-LSTM step at dt = 0  (c_dec == c exactly)
// ---------------------------------------------------------------------------
__global__ void final_ch_kernel() {
    int b = blockIdx.x, d = threadIdx.x;
    const int S = Bm * 64;
    int idx = b * 64 + d;
    float c = g_Gc[S + idx] * g_Clast[idx] + g_Gc[idx] * g_Gc[2 * S + idx];
    g_Hcur[idx] = g_Gc[3 * S + idx] * fast_tanh(c);
}

// ---------------------------------------------------------------------------
// Intensity MLP:  out[row] = softplus( gelu(h @ Wi1 + bi1) @ Wi2 + bi2 )
// One warp per row; 8 rows per 256-thread block.
// ---------------------------------------------------------------------------
__global__ __launch_bounds__(256) void intensity_kernel(const float* __restrict__ src, int M,
                                                        const float* __restrict__ W1,
                                                        const float* __restrict__ b1,
                                                        const float* __restrict__ W2,
                                                        const float* __restrict__ b2,
                                                        float* __restrict__ out) {
    __shared__ float W1s[64 * 32];
    __shared__ float W2s[32 * 6];
    __shared__ float b1s[32], b2s[6];
    __shared__ float rows[8][64];
    int tid = threadIdx.x;
    for (int i = tid; i < 2048; i += 256) W1s[i] = W1[i];
    if (tid < 192) W2s[tid] = W2[tid];
    if (tid < 32) b1s[tid] = b1[tid];
    if (tid < 6) b2s[tid] = b2[tid];
    __syncthreads();
    int warp = tid >> 5, lane = tid & 31;
    int r = blockIdx.x * 8 + warp;
    if (r >= M) return;
    rows[warp][lane] = src[(size_t)r * 64 + lane];
    rows[warp][lane + 32] = src[(size_t)r * 64 + lane + 32];
    __syncwarp();
    float acc = b1s[lane];
    #pragma unroll
    for (int k = 0; k < 64; k++) acc = fmaf(rows[warp][k], W1s[k * 32 + lane], acc);
    float y = fgelu(acc);
    #pragma unroll
    for (int c = 0; c < 6; c++) {
        float p = y * W2s[lane * 6 + c];
        #pragma unroll
        for (int off = 16; off; off >>= 1) p += __shfl_xor_sync(0xffffffffu, p, off);
        if (lane == 0) out[(size_t)r * 6 + c] = fsoftplus(p + b2s[c]);
    }
}

// ---------------------------------------------------------------------------
// TTE head: out[b] = softplus( gelu(h @ Wq1 + bq1) @ Wq2 + bq2 )
// ---------------------------------------------------------------------------
__global__ __launch_bounds__(256) void tte_kernel(const float* __restrict__ W1,
                                                  const float* __restrict__ b1,
                                                  const float* __restrict__ W2,
                                                  const float* __restrict__ b2,
                                                  float* __restrict__ out) {
    __shared__ float W1s[64 * 32];
    __shared__ float W2s[32];
    __shared__ float b1s[32];
    __shared__ float b2s0;
    __shared__ float rows[8][64];
    int tid = threadIdx.x;
    for (int i = tid; i < 2048; i += 256) W1s[i] = W1[i];
    if (tid < 32) { W2s[tid] = W2[tid]; b1s[tid] = b1[tid]; }
    if (tid == 0) b2s0 = b2[0];
    __syncthreads();
    int warp = tid >> 5, lane = tid & 31;
    int b = blockIdx.x * 8 + warp;
    if (b >= Bm) return;
    rows[warp][lane] = g_Hcur[b * 64 + lane];
    rows[warp][lane + 32] = g_Hcur[b * 64 + lane + 32];
    __syncwarp();
    float acc = b1s[lane];
    #pragma unroll
    for (int k = 0; k < 64; k++) acc = fmaf(rows[warp][k], W1s[k * 32 + lane], acc);
    float y = fgelu(acc);
    float p = y * W2s[lane];
    #pragma unroll
    for (int off = 16; off; off >>= 1) p += __shfl_xor_sync(0xffffffffu, p, off);
    if (lane == 0) out[b] = fsoftplus(p + b2s0);
}

// ---------------------------------------------------------------------------
// Direct head + softmax:  probs = softmax( gelu(cls@Ws1+bs1)@Ws2+bs2 + log(ci) )
// 4 batch rows per block, 384 threads.
// ---------------------------------------------------------------------------
__global__ __launch_bounds__(384) void direct_kernel(const float* __restrict__ cls,
                                                     const float* __restrict__ Ws1,
                                                     const float* __restrict__ bs1,
                                                     const float* __restrict__ Ws2,
                                                     const float* __restrict__ bs2,
                                                     const float* __restrict__ ci,
                                                     float* __restrict__ probs) {
    __shared__ float cls_s[4 * 768];
    __shared__ float s1[4][384];
    __shared__ float logit_s[4][6];
    int tid = threadIdx.x;
    int b0 = blockIdx.x * 4;
    for (int idx = tid; idx < 4 * 768; idx += 384)
        cls_s[idx] = cls[(size_t)b0 * 768 + idx];
    __syncthreads();
    float a0 = bs1[tid], a1 = a0, a2 = a0, a3 = a0;
    #pragma unroll 4
    for (int k = 0; k < 768; k++) {
        float w = Ws1[(size_t)k * 384 + tid];
        a0 = fmaf(cls_s[k], w, a0);
        a1 = fmaf(cls_s[768 + k], w, a1);
        a2 = fmaf(cls_s[1536 + k], w, a2);
        a3 = fmaf(cls_s[2304 + k], w, a3);
    }
    s1[0][tid] = fgelu(a0);
    s1[1][tid] = fgelu(a1);
    s1[2][tid] = fgelu(a2);
    s1[3][tid] = fgelu(a3);
    __syncthreads();
    int w = tid >> 5, lane = tid & 31;
    if (w < 6) {
        for (int g = 0; g < 4; g++) {
            float p = 0.f;
            #pragma unroll
            for (int j = lane; j < 384; j += 32) p = fmaf(s1[g][j], Ws2[(size_t)j * 6 + w], p);
            #pragma unroll
            for (int off = 16; off; off >>= 1) p += __shfl_xor_sync(0xffffffffu, p, off);
            if (lane == 0) logit_s[g][w] = p + bs2[w];
        }
    }
    __syncthreads();
    if (tid < 4) {
        int g = tid;
        float x[6], m = -1e30f;
        #pragma unroll
        for (int c = 0; c < 6; c++) {
            x[c] = logit_s[g][c] + logf(ci[(size_t)(b0 + g) * 6 + c]);
            m = fmaxf(m, x[c]);
        }
        float s = 0.f;
        #pragma unroll
        for (int c = 0; c < 6; c++) { x[c] = __expf(x[c] - m); s += x[c]; }
        float inv = __fdividef(1.f, s);
        #pragma unroll
        for (int c = 0; c < 6; c++) probs[(size_t)(b0 + g) * 6 + c] = x[c] * inv;
    }
}

// ---------------------------------------------------------------------------
// Launch
// ---------------------------------------------------------------------------
extern "C" void kernel_launch(void* const* d_in, const int* in_sizes, int n_in,
                              void* d_out, int out_size) {
    const float* cls   = (const float*)d_in[0];   // (256,768)
    const float* ev    = (const float*)d_in[1];   // (256,200,768)
    const float* days  = (const float*)d_in[2];   // (256,200)
    const float* We    = (const float*)d_in[3];   // (768,64)
    const float* be    = (const float*)d_in[4];
    const float* Wtime = (const float*)d_in[5];   // (1,64)
    const float* btime = (const float*)d_in[6];
    const float* Wg    = (const float*)d_in[7];   // (128,384)
    const float* bg    = (const float*)d_in[8];
    const float* Wi1   = (const float*)d_in[9];   // (64,32)
    const float* bi1   = (const float*)d_in[10];
    const float* Wi2   = (const float*)d_in[11];  // (32,6)
    const float* bi2   = (const float*)d_in[12];
    const float* Ws1   = (const float*)d_in[13];  // (768,384)
    const float* bs1   = (const float*)d_in[14];
    const float* Ws2   = (const float*)d_in[15];  // (384,6)
    const float* bs2   = (const float*)d_in[16];
    const float* Wq1   = (const float*)d_in[17];  // (64,32)
    const float* bq1   = (const float*)d_in[18];
    const float* Wq2   = (const float*)d_in[19];  // (32,1)
    const float* bq2   = (const float*)d_in[20];

    float* out = (float*)d_out;
    // Output packing: probs[1536] | tte[256] | current_intensity[1536] | history[307200]
    float* out_probs = out;
    float* out_tte   = out + 1536;
    float* out_ci    = out + 1536 + 256;
    float* out_hist  = out + 1536 + 256 + 1536;

    float *pE, *pG, *pEc, *pGc;
    cudaGetSymbolAddress((void**)&pE, g_E);
    cudaGetSymbolAddress((void**)&pG, g_G);
    cudaGetSymbolAddress((void**)&pEc, g_Ec);
    cudaGetSymbolAddress((void**)&pGc, g_Gc);

    setup_kernel<<<1, 384>>>(Wtime, btime, Wg, bg);

    gemm1_kernel<<<Mseq / 128, 256>>>(ev, We, be, pE);          // E for the sequence
    gemm1_kernel<<<Bm / 128, 256>>>(cls, We, be, pEc);          // e_cur

    gemm2_kernel<<<dim3(Mseq / 128, 3), 256>>>(pE, Wg, days, pG, Mseq);
    gemm2_kernel<<<dim3(Bm / 128, 3), 256>>>(pEc, Wg, nullptr, pGc, Bm);

    scan_kernel<<<(Bm * Dm) / 256, 256>>>(pG, days);
    final_ch_kernel<<<Bm, 64>>>();

    float* pHs;
    cudaGetSymbolAddress((void**)&pHs, g_Hs);
    float* pHcur;
    cudaGetSymbolAddress((void**)&pHcur, g_Hcur);

    intensity_kernel<<<Mseq / 8, 256>>>(pHs, Mseq, Wi1, bi1, Wi2, bi2, out_hist);
    intensity_kernel<<<Bm / 8, 256>>>(pHcur, Bm, Wi1, bi1, Wi2, bi2, out_ci);
    tte_kernel<<<Bm / 8, 256>>>(Wq1, bq1, Wq2, bq2, out_tte);
    direct_kernel<<<Bm / 4, 384>>>(cls, Ws1, bs1, Ws2, bs2, out_ci, out_probs);
}

// round 5
// speedup vs baseline: 1.2079x; 1.2079x over previous
#include <cuda_runtime.h>
#include <cuda_bf16.h>
#include <math.h>
#include <stdint.h>

// ---------------------------------------------------------------------------
// Problem constants
// ---------------------------------------------------------------------------
#define Bm 256
#define Lm 200
#define Hm 768
#define Dm 64
#define NS 6
#define Mseq (Bm * Lm)          // 51200
#define NC 8                    // scan chunks
#define CL 25                   // Lm / NC

typedef unsigned long long ull;

// ---------------------------------------------------------------------------
// Device scratch (static globals — no allocation allowed)
// ---------------------------------------------------------------------------
__device__ float g_E[(size_t)Mseq * Dm];            // E = ev@We+be
__device__ float g_G[(size_t)6 * Mseq * Dm];        // activated gates (gate, row, d)
__device__ float g_Hs[(size_t)Mseq * Dm];           // hidden states
__device__ float g_Ec[Bm * Dm];
__device__ float g_Gc[6 * Bm * Dm];
__device__ float g_Clast[Bm * Dm];
__device__ float g_Hcur[Bm * Dm];
__device__ float g_wt[384];                          // Wtime @ Wg_bot
__device__ float g_bias[384];                        // btime @ Wg_bot + bg
__device__ float g_scanP[Bm * Dm * NC];              // chunk prod(f)
__device__ float g_scanA[Bm * Dm * NC];              // chunk affine term
__device__ float g_scanCin[Bm * Dm * NC];            // chunk entry carry

// ---------------------------------------------------------------------------
// Math helpers
// ---------------------------------------------------------------------------
__device__ __forceinline__ float fast_tanh(float x) {
    float y;
    asm("tanh.approx.f32 %0, %1;" : "=f"(y) : "f"(x));
    return y;
}
__device__ __forceinline__ float fsigmoid(float x) {
    return __fdividef(1.0f, 1.0f + __expf(-x));
}
__device__ __forceinline__ float fsoftplus(float x) {
    return fmaxf(x, 0.0f) + log1pf(__expf(-fabsf(x)));
}
__device__ __forceinline__ float fgelu(float x) {
    return 0.5f * x * (1.0f + erff(x * 0.70710678118654752f));
}
// packed f32x2 helpers (exact fp32 semantics, 2 FMAs per instruction)
__device__ __forceinline__ void fma2(ull& d, ull a, ull b) {
    asm("fma.rn.f32x2 %0, %1, %2, %0;" : "+l"(d) : "l"(a), "l"(b));
}
__device__ __forceinline__ ull pack2(float x, float y) {
    ull r;
    asm("mov.b64 %0, {%1, %2};" : "=l"(r) : "f"(x), "f"(y));
    return r;
}
__device__ __forceinline__ float2 unpack2(ull v) {
    float2 r;
    asm("mov.b64 {%0, %1}, %2;" : "=f"(r.x), "=f"(r.y) : "l"(v));
    return r;
}

// ---------------------------------------------------------------------------
// Setup: wt[c] = sum_d Wtime[d]*Wg[64+d,c]; bias[c] = sum_d btime[d]*Wg[64+d,c] + bg[c]
// ---------------------------------------------------------------------------
__global__ void setup_kernel(const float* __restrict__ Wtime, const float* __restrict__ btime,
                             const float* __restrict__ Wg, const float* __restrict__ bg) {
    int c = threadIdx.x;   // 384 threads
    float s1 = 0.f, s2 = 0.f;
    #pragma unroll 8
    for (int d = 0; d < 64; d++) {
        float w = Wg[(size_t)(64 + d) * 384 + c];
        s1 += Wtime[d] * w;
        s2 += btime[d] * w;
    }
    g_wt[c] = s1;
    g_bias[c] = s2 + bg[c];
}

// ---------------------------------------------------------------------------
// GEMM1: C[M,64] = A[M,768] @ We[768,64] + be
// BM=128, BN=64, BK=16, 128 threads, 8x8/thread via f32x2, double-buffered.
// Outer loop unrolled x2 ONLY: keeps buffer index static but bounds code size
// (full unroll of 48 iters x ~550 instr was a compile-time / I$ hazard).
// ---------------------------------------------------------------------------
__global__ __launch_bounds__(128) void gemm1_kernel(const float* __restrict__ A,
                                                    const float* __restrict__ We,
                                                    const float* __restrict__ be,
                                                    float* __restrict__ C) {
    __shared__ __align__(16) float As[2][16][132];   // [k][m] transposed
    __shared__ __align__(16) float Bs[2][16][64];
    const int tid = threadIdx.x;
    const size_t r0 = (size_t)blockIdx.x * 128;
    const int tm = tid >> 3;   // 0..15 -> rows tm*8..+7
    const int tn = tid & 7;    // 0..7  -> cols tn*8..+7

    ull acc[4][8];
    #pragma unroll
    for (int i = 0; i < 4; i++)
        #pragma unroll
        for (int j = 0; j < 8; j++) acc[i][j] = 0ull;

    float4 ra[4], rb[2];
    // prologue: load tile 0
    #pragma unroll
    for (int p = 0; p < 4; p++) {
        int idx = tid + p * 128;
        int m = idx >> 2, kv = (idx & 3) * 4;
        ra[p] = *reinterpret_cast<const float4*>(A + (r0 + m) * 768 + kv);
    }
    #pragma unroll
    for (int q = 0; q < 2; q++) {
        int idx = tid + q * 128;
        int k = idx >> 4, nv = (idx & 15) * 4;
        rb[q] = *reinterpret_cast<const float4*>(We + (size_t)k * 64 + nv);
    }
    #pragma unroll
    for (int p = 0; p < 4; p++) {
        int idx = tid + p * 128;
        int m = idx >> 2, kv = (idx & 3) * 4;
        As[0][kv + 0][m] = ra[p].x; As[0][kv + 1][m] = ra[p].y;
        As[0][kv + 2][m] = ra[p].z; As[0][kv + 3][m] = ra[p].w;
    }
    #pragma unroll
    for (int q = 0; q < 2; q++) {
        int idx = tid + q * 128;
        int k = idx >> 4, nv = (idx & 15) * 4;
        *reinterpret_cast<float4*>(&Bs[0][k][nv]) = rb[q];
    }
    __syncthreads();

    #pragma unroll 2
    for (int t = 0; t < 48; t++) {
        int cur = t & 1;
        if (t < 47) {
            int k0 = (t + 1) * 16;
            #pragma unroll
            for (int p = 0; p < 4; p++) {
                int idx = tid + p * 128;
                int m = idx >> 2, kv = (idx & 3) * 4;
                ra[p] = *reinterpret_cast<const float4*>(A + (r0 + m) * 768 + k0 + kv);
            }
            #pragma unroll
            for (int q = 0; q < 2; q++) {
                int idx = tid + q * 128;
                int k = idx >> 4, nv = (idx & 15) * 4;
                rb[q] = *reinterpret_cast<const float4*>(We + (size_t)(k0 + k) * 64 + nv);
            }
        }
        #pragma unroll
        for (int kk = 0; kk < 16; kk++) {
            const ull* pa = reinterpret_cast<const ull*>(&As[cur][kk][tm * 8]);
            ull a0 = pa[0], a1 = pa[1], a2 = pa[2], a3 = pa[3];
            float4 bA = *reinterpret_cast<const float4*>(&Bs[cur][kk][tn * 8]);
            float4 bB = *reinterpret_cast<const float4*>(&Bs[cur][kk][tn * 8 + 4]);
            ull bp[8];
            bp[0] = pack2(bA.x, bA.x); bp[1] = pack2(bA.y, bA.y);
            bp[2] = pack2(bA.z, bA.z); bp[3] = pack2(bA.w, bA.w);
            bp[4] = pack2(bB.x, bB.x); bp[5] = pack2(bB.y, bB.y);
            bp[6] = pack2(bB.z, bB.z); bp[7] = pack2(bB.w, bB.w);
            #pragma unroll
            for (int j = 0; j < 8; j++) {
                fma2(acc[0][j], a0, bp[j]);
                fma2(acc[1][j], a1, bp[j]);
                fma2(acc[2][j], a2, bp[j]);
                fma2(acc[3][j], a3, bp[j]);
            }
        }
        if (t < 47) {
            int nxt = (t + 1) & 1;
            #pragma unroll
            for (int p = 0; p < 4; p++) {
                int idx = tid + p * 128;
                int m = idx >> 2, kv = (idx & 3) * 4;
                As[nxt][kv + 0][m] = ra[p].x; As[nxt][kv + 1][m] = ra[p].y;
                As[nxt][kv + 2][m] = ra[p].z; As[nxt][kv + 3][m] = ra[p].w;
            }
            #pragma unroll
            for (int q = 0; q < 2; q++) {
                int idx = tid + q * 128;
                int k = idx >> 4, nv = (idx & 15) * 4;
                *reinterpret_cast<float4*>(&Bs[nxt][k][nv]) = rb[q];
            }
        }
        __syncthreads();
    }

    float bb[8];
    #pragma unroll
    for (int j = 0; j < 8; j++) bb[j] = be[tn * 8 + j];
    #pragma unroll
    for (int i = 0; i < 4; i++) {
        float v0[8], v1[8];
        #pragma unroll
        for (int j = 0; j < 8; j++) {
            float2 u = unpack2(acc[i][j]);
            v0[j] = u.x + bb[j];
            v1[j] = u.y + bb[j];
        }
        size_t row0 = r0 + tm * 8 + 2 * i;
        *reinterpret_cast<float4*>(C + row0 * 64 + tn * 8)     = make_float4(v0[0], v0[1], v0[2], v0[3]);
        *reinterpret_cast<float4*>(C + row0 * 64 + tn * 8 + 4) = make_float4(v0[4], v0[5], v0[6], v0[7]);
        *reinterpret_cast<float4*>(C + (row0 + 1) * 64 + tn * 8)     = make_float4(v1[0], v1[1], v1[2], v1[3]);
        *reinterpret_cast<float4*>(C + (row0 + 1) * 64 + tn * 8 + 4) = make_float4(v1[4], v1[5], v1[6], v1[7]);
    }
}

// ---------------------------------------------------------------------------
// GEMM2: gates = act( E[M,64] @ Wg_top[64,384] + days[row]*wt + bias )
// BM=128, BN=128 (3 y-blocks), BK=16, 256 threads, 8x8/thread f32x2.
// Output: 6 planes gates[(gate*M + row)*64 + d], activation applied.
// ---------------------------------------------------------------------------
__global__ __launch_bounds__(256) void gemm2_kernel(const float* __restrict__ E,
                                                    const float* __restrict__ Wg,
                                                    const float* __restrict__ days,
                                                    float* __restrict__ gates, int M) {
    __shared__ __align__(16) float As[2][16][132];
    __shared__ __align__(16) float Bs[2][16][128];
    const int tid = threadIdx.x;
    const size_t r0 = (size_t)blockIdx.x * 128;
    const int n0 = blockIdx.y * 128;
    const int tm = tid >> 4;   // 0..15 -> rows tm*8..+7
    const int tn = tid & 15;   // 0..15 -> cols tn*8..+7

    ull acc[4][8];
    #pragma unroll
    for (int i = 0; i < 4; i++)
        #pragma unroll
        for (int j = 0; j < 8; j++) acc[i][j] = 0ull;

    float4 ra[2], rb[2];
    #pragma unroll
    for (int p = 0; p < 2; p++) {
        int idx = tid + p * 256;
        int m = idx >> 2, kv = (idx & 3) * 4;
        ra[p] = *reinterpret_cast<const float4*>(E + (r0 + m) * 64 + kv);
    }
    #pragma unroll
    for (int q = 0; q < 2; q++) {
        int idx = tid + q * 256;
        int k = idx >> 5, nv = (idx & 31) * 4;
        rb[q] = *reinterpret_cast<const float4*>(Wg + (size_t)k * 384 + n0 + nv);
    }
    #pragma unroll
    for (int p = 0; p < 2; p++) {
        int idx = tid + p * 256;
        int m = idx >> 2, kv = (idx & 3) * 4;
        As[0][kv + 0][m] = ra[p].x; As[0][kv + 1][m] = ra[p].y;
        As[0][kv + 2][m] = ra[p].z; As[0][kv + 3][m] = ra[p].w;
    }
    #pragma unroll
    for (int q = 0; q < 2; q++) {
        int idx = tid + q * 256;
        int k = idx >> 5, nv = (idx & 31) * 4;
        *reinterpret_cast<float4*>(&Bs[0][k][nv]) = rb[q];
    }
    __syncthreads();

    #pragma unroll 2
    for (int t = 0; t < 4; t++) {
        int cur = t & 1;
        if (t < 3) {
            int k0 = (t + 1) * 16;
            #pragma unroll
            for (int p = 0; p < 2; p++) {
                int idx = tid + p * 256;
                int m = idx >> 2, kv = (idx & 3) * 4;
                ra[p] = *reinterpret_cast<const float4*>(E + (r0 + m) * 64 + k0 + kv);
            }
            #pragma unroll
            for (int q = 0; q < 2; q++) {
                int idx = tid + q * 256;
                int k = idx >> 5, nv = (idx & 31) * 4;
                rb[q] = *reinterpret_cast<const float4*>(Wg + (size_t)(k0 + k) * 384 + n0 + nv);
            }
        }
        #pragma unroll
        for (int kk = 0; kk < 16; kk++) {
            const ull* pa = reinterpret_cast<const ull*>(&As[cur][kk][tm * 8]);
            ull a0 = pa[0], a1 = pa[1], a2 = pa[2], a3 = pa[3];
            float4 bA = *reinterpret_cast<const float4*>(&Bs[cur][kk][tn * 8]);
            float4 bB = *reinterpret_cast<const float4*>(&Bs[cur][kk][tn * 8 + 4]);
            ull bp[8];
            bp[0] = pack2(bA.x, bA.x); bp[1] = pack2(bA.y, bA.y);
            bp[2] = pack2(bA.z, bA.z); bp[3] = pack2(bA.w, bA.w);
            bp[4] = pack2(bB.x, bB.x); bp[5] = pack2(bB.y, bB.y);
            bp[6] = pack2(bB.z, bB.z); bp[7] = pack2(bB.w, bB.w);
            #pragma unroll
            for (int j = 0; j < 8; j++) {
                fma2(acc[0][j], a0, bp[j]);
                fma2(acc[1][j], a1, bp[j]);
                fma2(acc[2][j], a2, bp[j]);
                fma2(acc[3][j], a3, bp[j]);
            }
        }
        if (t < 3) {
            int nxt = (t + 1) & 1;
            #pragma unroll
            for (int p = 0; p < 2; p++) {
                int idx = tid + p * 256;
                int m = idx >> 2, kv = (idx & 3) * 4;
                As[nxt][kv + 0][m] = ra[p].x; As[nxt][kv + 1][m] = ra[p].y;
                As[nxt][kv + 2][m] = ra[p].z; As[nxt][kv + 3][m] = ra[p].w;
            }
            #pragma unroll
            for (int q = 0; q < 2; q++) {
                int idx = tid + q * 256;
                int k = idx >> 5, nv = (idx & 31) * 4;
                *reinterpret_cast<float4*>(&Bs[nxt][k][nv]) = rb[q];
            }
        }
        __syncthreads();
    }

    // Epilogue: bias + rank-1 time term + per-gate activation.
    const int cbase = n0 + tn * 8;         // cols cbase..cbase+7, all in one gate
    const int gate = cbase >> 6;
    const int d = cbase & 63;
    float wt8[8], bi8[8];
    #pragma unroll
    for (int j = 0; j < 8; j++) { wt8[j] = g_wt[cbase + j]; bi8[j] = g_bias[cbase + j]; }

    #pragma unroll
    for (int i = 0; i < 4; i++) {
        float2 u[8];
        #pragma unroll
        for (int j = 0; j < 8; j++) u[j] = unpack2(acc[i][j]);
        #pragma unroll
        for (int h = 0; h < 2; h++) {
            size_t rg = r0 + tm * 8 + 2 * i + h;
            float dy = days ? days[rg] : 0.f;
            float v[8];
            #pragma unroll
            for (int j = 0; j < 8; j++)
                v[j] = (h ? u[j].y : u[j].x) + bi8[j] + dy * wt8[j];
            if (gate == 2) {
                #pragma unroll
                for (int j = 0; j < 8; j++) v[j] = fast_tanh(v[j]);
            } else if (gate == 4) {
                #pragma unroll
                for (int j = 0; j < 8; j++) v[j] = fsoftplus(v[j]);
            } else if (gate != 5) {   // 0,1,3 -> sigmoid
                #pragma unroll
                for (int j = 0; j < 8; j++) v[j] = fsigmoid(v[j]);
            }
            float* dst = gates + ((size_t)gate * M + rg) * 64 + d;
            *reinterpret_cast<float4*>(dst)     = make_float4(v[0], v[1], v[2], v[3]);
            *reinterpret_cast<float4*>(dst + 4) = make_float4(v[4], v[5], v[6], v[7]);
        }
    }
}

// ---------------------------------------------------------------------------
// Chunk-parallel CT-LSTM scan:  c_l = f_l c_{l-1} + i_l z_l
// Phase A: per (b,d,chunk) compute P=prod f, A = chunk result with c_in=0
// Phase B: per (b,d) combine chunks serially -> entry carries + c_last
// Phase C: per (b,d,chunk) recompute c, emit h
// ---------------------------------------------------------------------------
__global__ __launch_bounds__(256) void scanA_kernel(const float* __restrict__ gates) {
    int t = blockIdx.x * 256 + threadIdx.x;   // 0..131071 : t = ch*16384 + b*64 + d
    int d = t & 63, rest = t >> 6;
    int b = rest & 255, ch = rest >> 8;
    const size_t S = (size_t)Mseq * 64;
    size_t base = ((size_t)(b * Lm + ch * CL)) * 64 + d;
    float c = 0.f, P = 1.f;
    #pragma unroll 5
    for (int l = 0; l < CL; l++) {
        size_t idx = base + (size_t)l * 64;
        float i_ = gates[idx];
        float f_ = gates[S + idx];
        float z_ = gates[2 * S + idx];
        c = f_ * c + i_ * z_;
        P *= f_;
    }
    g_scanA[t] = c;
    g_scanP[t] = P;
}

__global__ __launch_bounds__(256) void scanB_kernel() {
    int t = blockIdx.x * 256 + threadIdx.x;   // 0..16383 : b*64+d
    float c = 0.f;
    #pragma unroll
    for (int ch = 0; ch < NC; ch++) {
        int q = ch * 16384 + t;
        g_scanCin[q] = c;
        c = g_scanP[q] * c + g_scanA[q];
    }
    g_Clast[t] = c;
}

__global__ __launch_bounds__(256) void scanC_kernel(const float* __restrict__ gates,
                                                    const float* __restrict__ days) {
    int t = blockIdx.x * 256 + threadIdx.x;
    int d = t & 63, rest = t >> 6;
    int b = rest & 255, ch = rest >> 8;
    const size_t S = (size_t)Mseq * 64;
    size_t base = ((size_t)(b * Lm + ch * CL)) * 64 + d;
    const float* dptr = days + b * Lm + ch * CL;
    float c = g_scanCin[t];
    #pragma unroll 5
    for (int l = 0; l < CL; l++) {
        size_t idx = base + (size_t)l * 64;
        float i_ = gates[idx];
        float f_ = gates[S + idx];
        float z_ = gates[2 * S + idx];
        float o_ = gates[3 * S + idx];
        float dl = gates[4 * S + idx];
        float cb = gates[5 * S + idx];
        float dt = fmaxf(dptr[l], 0.f);
        c = f_ * c + i_ * z_;
        float e = __expf(-dl * dt);
        float cd = cb + (c - cb) * e;
        g_Hs[idx] = o_ * fast_tanh(cd);
    }
}

// ---------------------------------------------------------------------------
// Final CT-LSTM step at dt = 0  (c_dec == c exactly)
// ---------------------------------------------------------------------------
__global__ void final_ch_kernel() {
    int b = blockIdx.x, d = threadIdx.x;
    const int S = Bm * 64;
    int idx = b * 64 + d;
    float c = g_Gc[S + idx] * g_Clast[idx] + g_Gc[idx] * g_Gc[2 * S + idx];
    g_Hcur[idx] = g_Gc[3 * S + idx] * fast_tanh(c);
}

// ---------------------------------------------------------------------------
// Intensity MLP as block-tiled 2-layer GEMM (128 rows/block, 256 threads):
//   Y = gelu(h @ Wi1 + b1) [128x32];  out = softplus(Y @ Wi2 + b2) [128x6]
// Ys is ALIASED into the rows buffer (rows fully consumed before Ys written).
// ---------------------------------------------------------------------------
__global__ __launch_bounds__(256) void intensity_kernel(const float* __restrict__ src, int M,
                                                        const float* __restrict__ W1,
                                                        const float* __restrict__ b1,
                                                        const float* __restrict__ W2,
                                                        const float* __restrict__ b2,
                                                        float* __restrict__ out) {
    __shared__ __align__(16) float rows[128][68];    // 34816 B ; later reused as Ys[128][33]
    __shared__ __align__(16) float W1s[2048];        //  8192 B
    __shared__ float W2s[192], b1s[32], b2s[6];
    float* Ys = &rows[0][0];                         // pitch 33 (conflict-free layer-2 reads)
    int tid = threadIdx.x;
    size_t r0 = (size_t)blockIdx.x * 128;

    for (int i4 = tid; i4 < 512; i4 += 256)
        *reinterpret_cast<float4*>(&W1s[i4 * 4]) = reinterpret_cast<const float4*>(W1)[i4];
    if (tid < 192) W2s[tid] = W2[tid];
    if (tid < 32) b1s[tid] = b1[tid];
    if (tid < 6) b2s[tid] = b2[tid];
    #pragma unroll
    for (int p = 0; p < 8; p++) {
        int idx = tid + p * 256;
        int m = idx >> 4, dv = (idx & 15) * 4;
        *reinterpret_cast<float4*>(&rows[m][dv]) =
            *reinterpret_cast<const float4*>(src + (r0 + m) * 64 + dv);
    }
    __syncthreads();

    int tr = tid >> 3, tc = tid & 7;       // 32 x 8: 4 rows x 4 cols each
    float acc[4][4];
    #pragma unroll
    for (int i = 0; i < 4; i++)
        #pragma unroll
        for (int j = 0; j < 4; j++) acc[i][j] = b1s[tc * 4 + j];
    #pragma unroll 4
    for (int k = 0; k < 64; k++) {
        float4 w = *reinterpret_cast<const float4*>(&W1s[k * 32 + tc * 4]);
        float a0 = rows[tr * 4 + 0][k];
        float a1 = rows[tr * 4 + 1][k];
        float a2 = rows[tr * 4 + 2][k];
        float a3 = rows[tr * 4 + 3][k];
        acc[0][0] = fmaf(a0, w.x, acc[0][0]); acc[0][1] = fmaf(a0, w.y, acc[0][1]);
        acc[0][2] = fmaf(a0, w.z, acc[0][2]); acc[0][3] = fmaf(a0, w.w, acc[0][3]);
        acc[1][0] = fmaf(a1, w.x, acc[1][0]); acc[1][1] = fmaf(a1, w.y, acc[1][1]);
        acc[1][2] = fmaf(a1, w.z, acc[1][2]); acc[1][3] = fmaf(a1, w.w, acc[1][3]);
        acc[2][0] = fmaf(a2, w.x, acc[2][0]); acc[2][1] = fmaf(a2, w.y, acc[2][1]);
        acc[2][2] = fmaf(a2, w.z, acc[2][2]); acc[2][3] = fmaf(a2, w.w, acc[2][3]);
        acc[3][0] = fmaf(a3, w.x, acc[3][0]); acc[3][1] = fmaf(a3, w.y, acc[3][1]);
        acc[3][2] = fmaf(a3, w.z, acc[3][2]); acc[3][3] = fmaf(a3, w.w, acc[3][3]);
    }
    __syncthreads();   // all reads of rows complete before aliased Ys writes
    #pragma unroll
    for (int i = 0; i < 4; i++)
        #pragma unroll
        for (int j = 0; j < 4; j++)
            Ys[(tr * 4 + i) * 33 + tc * 4 + j] = fgelu(acc[i][j]);
    __syncthreads();

    if (tid < 128) {
        int row = tid;
        float o6[6];
        #pragma unroll
        for (int c = 0; c < 6; c++) o6[c] = b2s[c];
        #pragma unroll 4
        for (int k = 0; k < 32; k++) {
            float a = Ys[row * 33 + k];
            #pragma unroll
            for (int c = 0; c < 6; c++) o6[c] = fmaf(a, W2s[k * 6 + c], o6[c]);
        }
        #pragma unroll
        for (int c = 0; c < 6; c++) out[(r0 + row) * 6 + c] = fsoftplus(o6[c]);
    }
}

// ---------------------------------------------------------------------------
// TTE head: out[b] = softplus( gelu(h @ Wq1 + bq1) @ Wq2 + bq2 )
// ---------------------------------------------------------------------------
__global__ __launch_bounds__(256) void tte_kernel(const float* __restrict__ W1,
                                                  const float* __restrict__ b1,
                                                  const float* __restrict__ W2,
                                                  const float* __restrict__ b2,
                                                  float* __restrict__ out) {
    __shared__ float W1s[64 * 32];
    __shared__ float W2s[32];
    __shared__ float b1s[32];
    __shared__ float b2s0;
    __shared__ float rows[8][64];
    int tid = threadIdx.x;
    for (int i = tid; i < 2048; i += 256) W1s[i] = W1[i];
    if (tid < 32) { W2s[tid] = W2[tid]; b1s[tid] = b1[tid]; }
    if (tid == 0) b2s0 = b2[0];
    __syncthreads();
    int warp = tid >> 5, lane = tid & 31;
    int b = blockIdx.x * 8 + warp;
    if (b >= Bm) return;
    rows[warp][lane] = g_Hcur[b * 64 + lane];
    rows[warp][lane + 32] = g_Hcur[b * 64 + lane + 32];
    __syncwarp();
    float acc = b1s[lane];
    #pragma unroll
    for (int k = 0; k < 64; k++) acc = fmaf(rows[warp][k], W1s[k * 32 + lane], acc);
    float y = fgelu(acc);
    float p = y * W2s[lane];
    #pragma unroll
    for (int off = 16; off; off >>= 1) p += __shfl_xor_sync(0xffffffffu, p, off);
    if (lane == 0) out[b] = fsoftplus(p + b2s0);
}

// ---------------------------------------------------------------------------
// Direct head + softmax:  probs = softmax( gelu(cls@Ws1+bs1)@Ws2+bs2 + log(ci) )
// ---------------------------------------------------------------------------
__global__ __launch_bounds__(384) void direct_kernel(const float* __restrict__ cls,
                                                     const float* __restrict__ Ws1,
                                                     const float* __restrict__ bs1,
                                                     const float* __restrict__ Ws2,
                                                     const float* __restrict__ bs2,
                                                     const float* __restrict__ ci,
                                                     float* __restrict__ probs) {
    __shared__ float cls_s[4 * 768];
    __shared__ float s1[4][384];
    __shared__ float logit_s[4][6];
    int tid = threadIdx.x;
    int b0 = blockIdx.x * 4;
    for (int idx = tid; idx < 4 * 768; idx += 384)
        cls_s[idx] = cls[(size_t)b0 * 768 + idx];
    __syncthreads();
    float a0 = bs1[tid], a1 = a0, a2 = a0, a3 = a0;
    #pragma unroll 4
    for (int k = 0; k < 768; k++) {
        float w = Ws1[(size_t)k * 384 + tid];
        a0 = fmaf(cls_s[k], w, a0);
        a1 = fmaf(cls_s[768 + k], w, a1);
        a2 = fmaf(cls_s[1536 + k], w, a2);
        a3 = fmaf(cls_s[2304 + k], w, a3);
    }
    s1[0][tid] = fgelu(a0);
    s1[1][tid] = fgelu(a1);
    s1[2][tid] = fgelu(a2);
    s1[3][tid] = fgelu(a3);
    __syncthreads();
    int w = tid >> 5, lane = tid & 31;
    if (w < 6) {
        for (int g = 0; g < 4; g++) {
            float p = 0.f;
            #pragma unroll
            for (int j = lane; j < 384; j += 32) p = fmaf(s1[g][j], Ws2[(size_t)j * 6 + w], p);
            #pragma unroll
            for (int off = 16; off; off >>= 1) p += __shfl_xor_sync(0xffffffffu, p, off);
            if (lane == 0) logit_s[g][w] = p + bs2[w];
        }
    }
    __syncthreads();
    if (tid < 4) {
        int g = tid;
        float x[6], m = -1e30f;
        #pragma unroll
        for (int c = 0; c < 6; c++) {
            x[c] = logit_s[g][c] + logf(ci[(size_t)(b0 + g) * 6 + c]);
            m = fmaxf(m, x[c]);
        }
        float s = 0.f;
        #pragma unroll
        for (int c = 0; c < 6; c++) { x[c] = __expf(x[c] - m); s += x[c]; }
        float inv = __fdividef(1.f, s);
        #pragma unroll
        for (int c = 0; c < 6; c++) probs[(size_t)(b0 + g) * 6 + c] = x[c] * inv;
    }
}

// ---------------------------------------------------------------------------
// Launch
// ---------------------------------------------------------------------------
extern "C" void kernel_launch(void* const* d_in, const int* in_sizes, int n_in,
                              void* d_out, int out_size) {
    const float* cls   = (const float*)d_in[0];
    const float* ev    = (const float*)d_in[1];
    const float* days  = (const float*)d_in[2];
    const float* We    = (const float*)d_in[3];
    const float* be    = (const float*)d_in[4];
    const float* Wtime = (const float*)d_in[5];
    const float* btime = (const float*)d_in[6];
    const float* Wg    = (const float*)d_in[7];
    const float* bg    = (const float*)d_in[8];
    const float* Wi1   = (const float*)d_in[9];
    const float* bi1   = (const float*)d_in[10];
    const float* Wi2   = (const float*)d_in[11];
    const float* bi2   = (const float*)d_in[12];
    const float* Ws1   = (const float*)d_in[13];
    const float* bs1   = (const float*)d_in[14];
    const float* Ws2   = (const float*)d_in[15];
    const float* bs2   = (const float*)d_in[16];
    const float* Wq1   = (const float*)d_in[17];
    const float* bq1   = (const float*)d_in[18];
    const float* Wq2   = (const float*)d_in[19];
    const float* bq2   = (const float*)d_in[20];

    float* out = (float*)d_out;
    float* out_probs = out;
    float* out_tte   = out + 1536;
    float* out_ci    = out + 1536 + 256;
    float* out_hist  = out + 1536 + 256 + 1536;

    float *pE, *pG, *pEc, *pGc, *pHs, *pHcur;
    cudaGetSymbolAddress((void**)&pE, g_E);
    cudaGetSymbolAddress((void**)&pG, g_G);
    cudaGetSymbolAddress((void**)&pEc, g_Ec);
    cudaGetSymbolAddress((void**)&pGc, g_Gc);
    cudaGetSymbolAddress((void**)&pHs, g_Hs);
    cudaGetSymbolAddress((void**)&pHcur, g_Hcur);

    setup_kernel<<<1, 384>>>(Wtime, btime, Wg, bg);

    gemm1_kernel<<<Mseq / 128, 128>>>(ev, We, be, pE);
    gemm1_kernel<<<Bm / 128, 128>>>(cls, We, be, pEc);

    gemm2_kernel<<<dim3(Mseq / 128, 3), 256>>>(pE, Wg, days, pG, Mseq);
    gemm2_kernel<<<dim3(Bm / 128, 3), 256>>>(pEc, Wg, nullptr, pGc, Bm);

    scanA_kernel<<<(Bm * Dm * NC) / 256, 256>>>(pG);
    scanB_kernel<<<(Bm * Dm) / 256, 256>>>();
    scanC_kernel<<<(Bm * Dm * NC) / 256, 256>>>(pG, days);
    final_ch_kernel<<<Bm, 64>>>();

    intensity_kernel<<<Mseq / 128, 256>>>(pHs, Mseq, Wi1, bi1, Wi2, bi2, out_hist);
    intensity_kernel<<<Bm / 128, 256>>>(pHcur, Bm, Wi1, bi1, Wi2, bi2, out_ci);
    tte_kernel<<<Bm / 8, 256>>>(Wq1, bq1, Wq2, bq2, out_tte);
    direct_kernel<<<Bm / 4, 384>>>(cls, Ws1, bs1, Ws2, bs2, out_ci, out_probs);
}